// round 1
// baseline (speedup 1.0000x reference)
#include <cuda_runtime.h>
#include <cstdint>

#define BATCH 16
#define CH    512
#define NN    1681
#define CK    256
#define MQK   512
#define EPSV  1e-5f
#define SCALE 0.0625f   /* 256^-0.5 */

// ---------------- scratch (global __device__, allowed) ----------------
__device__ float g_Wqk[MQK * CH];                    // packed [Wq; Wk]  1 MB
__device__ float g_bias[MQK];
__device__ float g_QK[(size_t)BATCH * MQK * NN];     // Q rows 0..255, K rows 256..511  (55 MB)
__device__ float g_P[(size_t)BATCH * NN * NN];       // sim*scale*fg    (181 MB)
__device__ float g_minv[BATCH * NN];
__device__ float g_inv[BATCH * NN];

// ---------------- pack weights ----------------
__global__ void pack_kernel(const float* __restrict__ Wq, const float* __restrict__ bq,
                            const float* __restrict__ Wk, const float* __restrict__ bk) {
    int idx = blockIdx.x * blockDim.x + threadIdx.x;
    if (idx < MQK * CH) {
        int m = idx / CH, c = idx % CH;
        g_Wqk[idx] = (m < CK) ? Wq[m * CH + c] : Wk[(m - CK) * CH + c];
    }
    if (idx < MQK) g_bias[idx] = (idx < CK) ? bq[idx] : bk[idx - CK];
}

// ---------------- GEMM1: QK[b][m][n] = Wqk @ xf + bias ----------------
// M=512 (weights), N=1681 (pixels), K=512 (channels)
__global__ __launch_bounds__(256) void gemm1_kernel(const float* __restrict__ x) {
    __shared__ __align__(16) float As[8][132];
    __shared__ __align__(16) float Bs[8][132];
    const int b  = blockIdx.z;
    const int m0 = blockIdx.y * 128;
    const int n0 = blockIdx.x * 128;
    const int tid = threadIdx.x;
    const int tx = tid & 15, ty = tid >> 4;
    const float* xf = x + (size_t)b * CH * NN;

    float acc[8][8];
#pragma unroll
    for (int i = 0; i < 8; i++)
#pragma unroll
        for (int j = 0; j < 8; j++) acc[i][j] = 0.f;

    for (int k0 = 0; k0 < CH; k0 += 8) {
        // A: Wqk[(m0+m)][k0+k]   (k contiguous -> coalesced 32B segments)
#pragma unroll
        for (int i = 0; i < 4; i++) {
            int li = tid + i * 256;
            int k = li & 7, m = li >> 3;
            As[k][m] = g_Wqk[(m0 + m) * CH + k0 + k];
        }
        // B: xf[(k0+k)][n0+n]    (n contiguous -> fully coalesced)
#pragma unroll
        for (int i = 0; i < 4; i++) {
            int li = tid + i * 256;
            int n = li & 127, k = li >> 7;
            int gn = n0 + n;
            Bs[k][n] = (gn < NN) ? xf[(size_t)(k0 + k) * NN + gn] : 0.f;
        }
        __syncthreads();
#pragma unroll
        for (int kk = 0; kk < 8; kk++) {
            float4 a0 = *(const float4*)&As[kk][ty * 8];
            float4 a1 = *(const float4*)&As[kk][ty * 8 + 4];
            float a[8] = {a0.x, a0.y, a0.z, a0.w, a1.x, a1.y, a1.z, a1.w};
            float bb[8];
#pragma unroll
            for (int j = 0; j < 8; j++) bb[j] = Bs[kk][tx + j * 16];
#pragma unroll
            for (int i = 0; i < 8; i++)
#pragma unroll
                for (int j = 0; j < 8; j++) acc[i][j] += a[i] * bb[j];
        }
        __syncthreads();
    }

    float* outp = g_QK + (size_t)b * MQK * NN;
#pragma unroll
    for (int i = 0; i < 8; i++) {
        int m = m0 + ty * 8 + i;
        float bias = g_bias[m];
#pragma unroll
        for (int j = 0; j < 8; j++) {
            int n = n0 + tx + j * 16;
            if (n < NN) outp[(size_t)m * NN + n] = acc[i][j] + bias;
        }
    }
}

// ---------------- GEMM2: P[b][n][m] = (Q^T K) * scale * fg ----------------
// M=N=1681, K=256
__global__ __launch_bounds__(256) void gemm2_kernel(const float* __restrict__ fg) {
    __shared__ __align__(16) float As[8][132];
    __shared__ __align__(16) float Bs[8][132];
    const int b  = blockIdx.z;
    const int n0 = blockIdx.y * 128;   // output rows
    const int m0 = blockIdx.x * 128;   // output cols
    const int tid = threadIdx.x;
    const int tx = tid & 15, ty = tid >> 4;
    const float* Q  = g_QK + (size_t)b * MQK * NN;
    const float* Kp = Q + (size_t)CK * NN;

    float acc[8][8];
#pragma unroll
    for (int i = 0; i < 8; i++)
#pragma unroll
        for (int j = 0; j < 8; j++) acc[i][j] = 0.f;

    for (int k0 = 0; k0 < CK; k0 += 8) {
#pragma unroll
        for (int i = 0; i < 4; i++) {
            int li = tid + i * 256;
            int n = li & 127, k = li >> 7;
            int gn = n0 + n;
            As[k][n] = (gn < NN) ? Q[(size_t)(k0 + k) * NN + gn] : 0.f;
        }
#pragma unroll
        for (int i = 0; i < 4; i++) {
            int li = tid + i * 256;
            int m = li & 127, k = li >> 7;
            int gm = m0 + m;
            Bs[k][m] = (gm < NN) ? Kp[(size_t)(k0 + k) * NN + gm] : 0.f;
        }
        __syncthreads();
#pragma unroll
        for (int kk = 0; kk < 8; kk++) {
            float4 a0 = *(const float4*)&As[kk][ty * 8];
            float4 a1 = *(const float4*)&As[kk][ty * 8 + 4];
            float a[8] = {a0.x, a0.y, a0.z, a0.w, a1.x, a1.y, a1.z, a1.w};
            float bb[8];
#pragma unroll
            for (int j = 0; j < 8; j++) bb[j] = Bs[kk][tx + j * 16];
#pragma unroll
            for (int i = 0; i < 8; i++)
#pragma unroll
                for (int j = 0; j < 8; j++) acc[i][j] += a[i] * bb[j];
        }
        __syncthreads();
    }

    const float* FG = fg + (size_t)b * NN * NN;
    float* Pp = g_P + (size_t)b * NN * NN;
#pragma unroll
    for (int i = 0; i < 8; i++) {
        int n = n0 + ty * 8 + i;
        if (n >= NN) continue;
        size_t row = (size_t)n * NN;
#pragma unroll
        for (int j = 0; j < 8; j++) {
            int m = m0 + tx + j * 16;
            if (m < NN) Pp[row + m] = acc[i][j] * SCALE * FG[row + m];
        }
    }
}

// ---------------- row stats: min(P), s1=sum(P*fg), s2=sum(fg) ----------------
__global__ __launch_bounds__(256) void stats_kernel(const float* __restrict__ fg) {
    const int b = blockIdx.y, n = blockIdx.x;
    const int tid = threadIdx.x;
    const float* Pr = g_P + ((size_t)b * NN + n) * NN;
    const float* Fr = fg + ((size_t)b * NN + n) * NN;
    float mn = 3.4e38f, s1 = 0.f, s2 = 0.f;
    for (int m = tid; m < NN; m += 256) {
        float p = Pr[m], f = Fr[m];
        mn = fminf(mn, p);
        s1 += p * f;
        s2 += f;
    }
    __shared__ float sm[256], sa[256], sb[256];
    sm[tid] = mn; sa[tid] = s1; sb[tid] = s2;
    __syncthreads();
    for (int s = 128; s > 0; s >>= 1) {
        if (tid < s) {
            sm[tid] = fminf(sm[tid], sm[tid + s]);
            sa[tid] += sa[tid + s];
            sb[tid] += sb[tid + s];
        }
        __syncthreads();
    }
    if (tid == 0) {
        g_minv[b * NN + n] = sm[0];
        g_inv[b * NN + n] = 1.f / (sa[0] - sm[0] * sb[0] + EPSV);
    }
}

// ---------------- GEMM3: out = gamma * (sim_final @ V) + x ----------------
// rows n (1681), cols c (512), K = m (1681); sim_final computed on the fly.
__global__ __launch_bounds__(256) void gemm3_kernel(const float* __restrict__ x,
                                                    const float* __restrict__ fg,
                                                    const float* __restrict__ bg,
                                                    const float* __restrict__ gamma,
                                                    float* __restrict__ out) {
    __shared__ __align__(16) float As[8][132];
    __shared__ __align__(16) float Bs[8][132];
    __shared__ float rMin[128], rInv[128];
    const int b  = blockIdx.z;
    const int n0 = blockIdx.y * 128;
    const int c0 = blockIdx.x * 128;
    const int tid = threadIdx.x;
    const int tx = tid & 15, ty = tid >> 4;

    if (tid < 128) {
        int n = n0 + tid;
        rMin[tid] = (n < NN) ? g_minv[b * NN + n] : 0.f;
        rInv[tid] = (n < NN) ? g_inv[b * NN + n] : 0.f;
    }
    __syncthreads();

    const float* P  = g_P + (size_t)b * NN * NN;
    const float* FG = fg + (size_t)b * NN * NN;
    const float* BG = bg + (size_t)b * NN * NN;
    const float* xf = x + (size_t)b * CH * NN;

    float acc[8][8];
#pragma unroll
    for (int i = 0; i < 8; i++)
#pragma unroll
        for (int j = 0; j < 8; j++) acc[i][j] = 0.f;

    for (int m0 = 0; m0 < NN; m0 += 8) {
        // A: sim_final[n0+n][m0+k] computed on the fly
#pragma unroll
        for (int i = 0; i < 4; i++) {
            int li = tid + i * 256;
            int k = li & 7, n = li >> 3;
            int gn = n0 + n, gm = m0 + k;
            float v = 0.f;
            if (gn < NN && gm < NN) {
                size_t a = (size_t)gn * NN + gm;
                v = (P[a] - rMin[n]) * FG[a] * rInv[n] + BG[a];
            }
            As[k][n] = v;
        }
        // B: V[m0+k][c0+c] = xf[c0+c][m0+k]   (m contiguous -> 32B segments)
#pragma unroll
        for (int i = 0; i < 4; i++) {
            int li = tid + i * 256;
            int k = li & 7, c = li >> 3;
            int gm = m0 + k;
            Bs[k][c] = (gm < NN) ? xf[(size_t)(c0 + c) * NN + gm] : 0.f;
        }
        __syncthreads();
#pragma unroll
        for (int kk = 0; kk < 8; kk++) {
            float4 a0 = *(const float4*)&As[kk][ty * 8];
            float4 a1 = *(const float4*)&As[kk][ty * 8 + 4];
            float a[8] = {a0.x, a0.y, a0.z, a0.w, a1.x, a1.y, a1.z, a1.w};
            float bb[8];
#pragma unroll
            for (int j = 0; j < 8; j++) bb[j] = Bs[kk][tx + j * 16];
#pragma unroll
            for (int i = 0; i < 8; i++)
#pragma unroll
                for (int j = 0; j < 8; j++) acc[i][j] += a[i] * bb[j];
        }
        __syncthreads();
    }

    const float g = gamma[0];
    float* outb = out + (size_t)b * CH * NN;
#pragma unroll
    for (int i = 0; i < 8; i++) {
        int n = n0 + ty * 8 + i;
        if (n >= NN) continue;
#pragma unroll
        for (int j = 0; j < 8; j++) {
            int c = c0 + tx + j * 16;
            size_t idx = (size_t)c * NN + n;
            outb[idx] = g * acc[i][j] + xf[idx];
        }
    }
}

// ---------------- launch ----------------
extern "C" void kernel_launch(void* const* d_in, const int* in_sizes, int n_in,
                              void* d_out, int out_size) {
    const float* x     = (const float*)d_in[0];
    const float* fg    = (const float*)d_in[1];
    const float* bg    = (const float*)d_in[2];
    const float* Wq    = (const float*)d_in[3];
    const float* bq    = (const float*)d_in[4];
    const float* Wk    = (const float*)d_in[5];
    const float* bk    = (const float*)d_in[6];
    const float* gamma = (const float*)d_in[7];
    float* out = (float*)d_out;

    pack_kernel<<<(MQK * CH + 255) / 256, 256>>>(Wq, bq, Wk, bk);

    dim3 g1((NN + 127) / 128, MQK / 128, BATCH);
    gemm1_kernel<<<g1, 256>>>(x);

    dim3 g2((NN + 127) / 128, (NN + 127) / 128, BATCH);
    gemm2_kernel<<<g2, 256>>>(fg);

    stats_kernel<<<dim3(NN, BATCH), 256>>>(fg);

    dim3 g3(CH / 128, (NN + 127) / 128, BATCH);
    gemm3_kernel<<<g3, 256>>>(x, fg, bg, gamma, out);
}

// round 2
// speedup vs baseline: 1.5581x; 1.5581x over previous
#include <cuda_runtime.h>
#include <cstdint>
#include <cfloat>

#define BATCH 16
#define CH    512
#define NN    1681
#define CK    256
#define MQK   512
#define EPSV  1e-5f
#define SCALE 0.0625f   /* 256^-0.5 */

// ---------------- scratch ----------------
__device__ float g_Wqk[MQK * CH];
__device__ float g_bias[MQK];
__device__ float g_QK[(size_t)BATCH * MQK * NN];     // Q rows 0..255, K rows 256..511
__device__ float g_P[(size_t)BATCH * NN * NN];       // sim*scale*fg
__device__ float g_minv[BATCH * NN];
__device__ float g_s1[BATCH * NN];
__device__ float g_s2[BATCH * NN];
__device__ float g_inv[BATCH * NN];

// ---------------- helpers ----------------
__device__ __forceinline__ uint32_t f2tf(float f) {
    uint32_t u;
    asm("cvt.rna.tf32.f32 %0, %1;" : "=r"(u) : "f"(f));
    return u;
}

__device__ __forceinline__ void mma_tf32(float c[4], const uint32_t a[4], const uint32_t b[2]) {
    asm volatile(
        "mma.sync.aligned.m16n8k8.row.col.f32.tf32.tf32.f32 "
        "{%0,%1,%2,%3}, {%4,%5,%6,%7}, {%8,%9}, {%0,%1,%2,%3};\n"
        : "+f"(c[0]), "+f"(c[1]), "+f"(c[2]), "+f"(c[3])
        : "r"(a[0]), "r"(a[1]), "r"(a[2]), "r"(a[3]), "r"(b[0]), "r"(b[1]));
}

__device__ __forceinline__ void atomicMinFloat(float* addr, float value) {
    if (value >= 0.f)
        atomicMin((int*)addr, __float_as_int(value));
    else
        atomicMax((unsigned int*)addr, __float_as_uint(value));
}

// ---------------- pack weights + reset stats ----------------
__global__ void pack_kernel(const float* __restrict__ Wq, const float* __restrict__ bq,
                            const float* __restrict__ Wk, const float* __restrict__ bk) {
    int idx = blockIdx.x * blockDim.x + threadIdx.x;
    if (idx < MQK * CH) {
        int m = idx / CH, c = idx % CH;
        g_Wqk[idx] = (m < CK) ? Wq[m * CH + c] : Wk[(m - CK) * CH + c];
    }
    if (idx < MQK) g_bias[idx] = (idx < CK) ? bq[idx] : bk[idx - CK];
    if (idx < BATCH * NN) {
        g_minv[idx] = FLT_MAX;
        g_s1[idx] = 0.f;
        g_s2[idx] = 0.f;
    }
}

// =====================================================================
// GEMM1: QK[b][m][n] = Wqk @ xf + bias    M=512, N=1681, K=512
// =====================================================================
__global__ __launch_bounds__(256) void gemm1_kernel(const float* __restrict__ x) {
    __shared__ uint32_t As[16][132];
    __shared__ uint32_t Bs[16][132];
    const int b  = blockIdx.z;
    const int m0 = blockIdx.y * 128;
    const int n0 = blockIdx.x * 128;
    const int tid = threadIdx.x;
    const int lane = tid & 31, wid = tid >> 5;
    const int warp_m = wid >> 1, warp_n = wid & 1;
    const int r = lane >> 2, cc = lane & 3;
    const float* xf = x + (size_t)b * CH * NN;

    float acc[2][8][4];
#pragma unroll
    for (int i = 0; i < 2; i++)
#pragma unroll
        for (int j = 0; j < 8; j++)
#pragma unroll
            for (int q = 0; q < 4; q++) acc[i][j][q] = 0.f;

    for (int k0 = 0; k0 < CH; k0 += 16) {
#pragma unroll
        for (int i = 0; i < 8; i++) {
            int li = tid + i * 256;
            int kc = li & 15, m = li >> 4;
            As[kc][m] = f2tf(g_Wqk[(m0 + m) * CH + k0 + kc]);
        }
#pragma unroll
        for (int i = 0; i < 8; i++) {
            int li = tid + i * 256;
            int n = li & 127, kc = li >> 7;
            int gn = n0 + n;
            Bs[kc][n] = f2tf(gn < NN ? xf[(size_t)(k0 + kc) * NN + gn] : 0.f);
        }
        __syncthreads();
#pragma unroll
        for (int kk = 0; kk < 16; kk += 8) {
            uint32_t af[2][4], bf[8][2];
#pragma unroll
            for (int i = 0; i < 2; i++) {
                int m = warp_m * 32 + i * 16 + r;
                af[i][0] = As[kk + cc][m];
                af[i][1] = As[kk + cc][m + 8];
                af[i][2] = As[kk + cc + 4][m];
                af[i][3] = As[kk + cc + 4][m + 8];
            }
#pragma unroll
            for (int j = 0; j < 8; j++) {
                int n = warp_n * 64 + j * 8 + r;
                bf[j][0] = Bs[kk + cc][n];
                bf[j][1] = Bs[kk + cc + 4][n];
            }
#pragma unroll
            for (int i = 0; i < 2; i++)
#pragma unroll
                for (int j = 0; j < 8; j++) mma_tf32(acc[i][j], af[i], bf[j]);
        }
        __syncthreads();
    }

    float* outp = g_QK + (size_t)b * MQK * NN;
#pragma unroll
    for (int i = 0; i < 2; i++) {
#pragma unroll
        for (int h = 0; h < 2; h++) {
            int m = m0 + warp_m * 32 + i * 16 + r + h * 8;
            float bias = g_bias[m];
#pragma unroll
            for (int j = 0; j < 8; j++) {
                int n = n0 + warp_n * 64 + j * 8 + 2 * cc;
                if (n < NN)     outp[(size_t)m * NN + n]     = acc[i][j][2 * h]     + bias;
                if (n + 1 < NN) outp[(size_t)m * NN + n + 1] = acc[i][j][2 * h + 1] + bias;
            }
        }
    }
}

// =====================================================================
// GEMM2: P[b][n][m] = (Q^T K)*scale*fg ; fused row stats (min, s1, s2)
// =====================================================================
__global__ __launch_bounds__(256) void gemm2_kernel(const float* __restrict__ fg) {
    __shared__ uint32_t As[16][132];
    __shared__ uint32_t Bs[16][132];
    const int b  = blockIdx.z;
    const int n0 = blockIdx.y * 128;   // output rows (query)
    const int m0 = blockIdx.x * 128;   // output cols (key)
    const int tid = threadIdx.x;
    const int lane = tid & 31, wid = tid >> 5;
    const int warp_m = wid >> 1, warp_n = wid & 1;
    const int r = lane >> 2, cc = lane & 3;
    const float* Q  = g_QK + (size_t)b * MQK * NN;
    const float* Kp = Q + (size_t)CK * NN;

    float acc[2][8][4];
#pragma unroll
    for (int i = 0; i < 2; i++)
#pragma unroll
        for (int j = 0; j < 8; j++)
#pragma unroll
            for (int q = 0; q < 4; q++) acc[i][j][q] = 0.f;

    for (int k0 = 0; k0 < CK; k0 += 16) {
#pragma unroll
        for (int i = 0; i < 8; i++) {
            int li = tid + i * 256;
            int n = li & 127, kc = li >> 7;
            int gn = n0 + n;
            As[kc][n] = f2tf(gn < NN ? Q[(size_t)(k0 + kc) * NN + gn] : 0.f);
        }
#pragma unroll
        for (int i = 0; i < 8; i++) {
            int li = tid + i * 256;
            int m = li & 127, kc = li >> 7;
            int gm = m0 + m;
            Bs[kc][m] = f2tf(gm < NN ? Kp[(size_t)(k0 + kc) * NN + gm] : 0.f);
        }
        __syncthreads();
#pragma unroll
        for (int kk = 0; kk < 16; kk += 8) {
            uint32_t af[2][4], bf[8][2];
#pragma unroll
            for (int i = 0; i < 2; i++) {
                int m = warp_m * 32 + i * 16 + r;
                af[i][0] = As[kk + cc][m];
                af[i][1] = As[kk + cc][m + 8];
                af[i][2] = As[kk + cc + 4][m];
                af[i][3] = As[kk + cc + 4][m + 8];
            }
#pragma unroll
            for (int j = 0; j < 8; j++) {
                int n = warp_n * 64 + j * 8 + r;
                bf[j][0] = Bs[kk + cc][n];
                bf[j][1] = Bs[kk + cc + 4][n];
            }
#pragma unroll
            for (int i = 0; i < 2; i++)
#pragma unroll
                for (int j = 0; j < 8; j++) mma_tf32(acc[i][j], af[i], bf[j]);
        }
        __syncthreads();
    }

    const float* FG = fg + (size_t)b * NN * NN;
    float* Pp = g_P + (size_t)b * NN * NN;
#pragma unroll
    for (int i = 0; i < 2; i++) {
#pragma unroll
        for (int h = 0; h < 2; h++) {
            int gn = n0 + warp_m * 32 + i * 16 + r + h * 8;
            bool rowvalid = gn < NN;
            size_t rowoff = (size_t)gn * NN;
            float mn = FLT_MAX, s1 = 0.f, s2 = 0.f;
#pragma unroll
            for (int j = 0; j < 8; j++) {
                int gm = m0 + warp_n * 64 + j * 8 + 2 * cc;
                if (rowvalid && gm < NN) {
                    float f = FG[rowoff + gm];
                    float p = acc[i][j][2 * h] * SCALE * f;
                    Pp[rowoff + gm] = p;
                    mn = fminf(mn, p); s1 += p * f; s2 += f;
                }
                if (rowvalid && gm + 1 < NN) {
                    float f = FG[rowoff + gm + 1];
                    float p = acc[i][j][2 * h + 1] * SCALE * f;
                    Pp[rowoff + gm + 1] = p;
                    mn = fminf(mn, p); s1 += p * f; s2 += f;
                }
            }
            // reduce across the 4 lanes (cc = 0..3) sharing this row
            mn = fminf(mn, __shfl_xor_sync(0xffffffffu, mn, 1));
            mn = fminf(mn, __shfl_xor_sync(0xffffffffu, mn, 2));
            s1 += __shfl_xor_sync(0xffffffffu, s1, 1);
            s1 += __shfl_xor_sync(0xffffffffu, s1, 2);
            s2 += __shfl_xor_sync(0xffffffffu, s2, 1);
            s2 += __shfl_xor_sync(0xffffffffu, s2, 2);
            if (cc == 0 && rowvalid) {
                atomicMinFloat(&g_minv[b * NN + gn], mn);
                atomicAdd(&g_s1[b * NN + gn], s1);
                atomicAdd(&g_s2[b * NN + gn], s2);
            }
        }
    }
}

// ---------------- finalize: inv = 1/(s1 - min*s2 + eps) ----------------
__global__ void finalize_kernel() {
    int idx = blockIdx.x * blockDim.x + threadIdx.x;
    if (idx < BATCH * NN)
        g_inv[idx] = 1.f / (g_s1[idx] - g_minv[idx] * g_s2[idx] + EPSV);
}

// =====================================================================
// GEMM3: out = gamma * (sim_final @ V) + x  (sim_final on the fly)
// rows n (1681), cols c (512), K = m (1681)
// =====================================================================
__global__ __launch_bounds__(256) void gemm3_kernel(const float* __restrict__ x,
                                                    const float* __restrict__ fg,
                                                    const float* __restrict__ bg,
                                                    const float* __restrict__ gamma,
                                                    float* __restrict__ out) {
    __shared__ uint32_t As[16][132];
    __shared__ uint32_t Bs[16][132];
    __shared__ float rMin[128], rInv[128];
    const int b  = blockIdx.z;
    const int n0 = blockIdx.y * 128;
    const int c0 = blockIdx.x * 128;
    const int tid = threadIdx.x;
    const int lane = tid & 31, wid = tid >> 5;
    const int warp_m = wid >> 1, warp_n = wid & 1;
    const int r = lane >> 2, cc = lane & 3;

    if (tid < 128) {
        int n = n0 + tid;
        rMin[tid] = (n < NN) ? g_minv[b * NN + n] : 0.f;
        rInv[tid] = (n < NN) ? g_inv[b * NN + n] : 0.f;
    }
    __syncthreads();

    const float* P  = g_P + (size_t)b * NN * NN;
    const float* FG = fg + (size_t)b * NN * NN;
    const float* BG = bg + (size_t)b * NN * NN;
    const float* xf = x + (size_t)b * CH * NN;

    float acc[2][8][4];
#pragma unroll
    for (int i = 0; i < 2; i++)
#pragma unroll
        for (int j = 0; j < 8; j++)
#pragma unroll
            for (int q = 0; q < 4; q++) acc[i][j][q] = 0.f;

    for (int m0 = 0; m0 < NN; m0 += 16) {
        // A: sim_final[n0+n][m0+kc] on the fly
#pragma unroll
        for (int i = 0; i < 8; i++) {
            int li = tid + i * 256;
            int kc = li & 15, n = li >> 4;
            int gn = n0 + n, gm = m0 + kc;
            float v = 0.f;
            if (gn < NN && gm < NN) {
                size_t a = (size_t)gn * NN + gm;
                v = (P[a] - rMin[n]) * FG[a] * rInv[n] + BG[a];
            }
            As[kc][n] = f2tf(v);
        }
        // B: V[m0+kc][c0+c] = xf[c0+c][m0+kc]
#pragma unroll
        for (int i = 0; i < 8; i++) {
            int li = tid + i * 256;
            int kc = li & 15, c = li >> 4;
            int gm = m0 + kc;
            Bs[kc][c] = f2tf(gm < NN ? xf[(size_t)(c0 + c) * NN + gm] : 0.f);
        }
        __syncthreads();
#pragma unroll
        for (int kk = 0; kk < 16; kk += 8) {
            uint32_t af[2][4], bf[8][2];
#pragma unroll
            for (int i = 0; i < 2; i++) {
                int m = warp_m * 32 + i * 16 + r;
                af[i][0] = As[kk + cc][m];
                af[i][1] = As[kk + cc][m + 8];
                af[i][2] = As[kk + cc + 4][m];
                af[i][3] = As[kk + cc + 4][m + 8];
            }
#pragma unroll
            for (int j = 0; j < 8; j++) {
                int n = warp_n * 64 + j * 8 + r;
                bf[j][0] = Bs[kk + cc][n];
                bf[j][1] = Bs[kk + cc + 4][n];
            }
#pragma unroll
            for (int i = 0; i < 2; i++)
#pragma unroll
                for (int j = 0; j < 8; j++) mma_tf32(acc[i][j], af[i], bf[j]);
        }
        __syncthreads();
    }

    const float g = gamma[0];
    float* outb = out + (size_t)b * CH * NN;
#pragma unroll
    for (int i = 0; i < 2; i++) {
#pragma unroll
        for (int h = 0; h < 2; h++) {
            int gn = n0 + warp_m * 32 + i * 16 + r + h * 8;
            if (gn >= NN) continue;
#pragma unroll
            for (int j = 0; j < 8; j++) {
                int gc = c0 + warp_n * 64 + j * 8 + 2 * cc;
                size_t i0 = (size_t)gc * NN + gn;
                size_t i1 = (size_t)(gc + 1) * NN + gn;
                outb[i0] = g * acc[i][j][2 * h]     + xf[i0];
                outb[i1] = g * acc[i][j][2 * h + 1] + xf[i1];
            }
        }
    }
}

// ---------------- launch ----------------
extern "C" void kernel_launch(void* const* d_in, const int* in_sizes, int n_in,
                              void* d_out, int out_size) {
    const float* x     = (const float*)d_in[0];
    const float* fg    = (const float*)d_in[1];
    const float* bg    = (const float*)d_in[2];
    const float* Wq    = (const float*)d_in[3];
    const float* bq    = (const float*)d_in[4];
    const float* Wk    = (const float*)d_in[5];
    const float* bk    = (const float*)d_in[6];
    const float* gamma = (const float*)d_in[7];
    float* out = (float*)d_out;

    pack_kernel<<<(MQK * CH + 255) / 256, 256>>>(Wq, bq, Wk, bk);

    dim3 g1((NN + 127) / 128, MQK / 128, BATCH);
    gemm1_kernel<<<g1, 256>>>(x);

    dim3 g2((NN + 127) / 128, (NN + 127) / 128, BATCH);
    gemm2_kernel<<<g2, 256>>>(fg);

    finalize_kernel<<<(BATCH * NN + 255) / 256, 256>>>();

    dim3 g3(CH / 128, (NN + 127) / 128, BATCH);
    gemm3_kernel<<<g3, 256>>>(x, fg, bg, gamma, out);
}